// round 11
// baseline (speedup 1.0000x reference)
#include <cuda_runtime.h>
#include <cstdio>

#define NN 50000
#define NE 800000
#define FI 128
#define FH 128
#define FC 64

// ---------------- scratch (device globals; no allocation allowed) ----------------
__device__ int   g_cntI[NN];                       // in-degree (int)
__device__ int   g_off[NN + 1];                    // CSR offsets (by dst)
__device__ int   g_cur[NN];                        // fill cursors
__device__ int   g_csrc[NE];                       // CSR src lists
__device__ float g_cnt[NN];                        // in-degree (float)
__device__ float g_dinv[NN];                       // rsqrt(in-degree + 1) for GCN
__device__ __align__(16) float g_agg[NN * FI];     // gather accumulator (both SAGE layers)
__device__ __align__(16) float g_h1[NN * FH];      // SAGE1 output (post-relu)
__device__ __align__(16) float g_h2[NN * FC];      // SAGE2 output (post-softmax)
__device__ __align__(16) float g_xw[NN * FC];      // h2 @ Wg

// ---------------- CSR build ----------------
// edge_index arrives as INT32 [2, E] (harness supports fp32/int32/bf16 only;
// the reference's int64 is downcast). Reading it as int64 was the root cause
// of every prior fault (OOB reads + wild atomic addresses).
__global__ void k_zero_cnt() {
    int i = blockIdx.x * blockDim.x + threadIdx.x;
    if (i < NN) g_cntI[i] = 0;
}

__global__ void k_count(const int* __restrict__ ei) {
    int e = blockIdx.x * blockDim.x + threadIdx.x;
    if (e < NE) atomicAdd(g_cntI + ei[NE + e], 1);
}

// single-block exclusive scan over NN counts -> offsets (+ cursor copy)
__global__ void k_scan() {
    __shared__ int part[1024];
    const int CH = (NN + 1023) / 1024;   // 49
    int t = threadIdx.x;
    int base = t * CH;
    int sum = 0;
    for (int i = 0; i < CH; i++) {
        int idx = base + i;
        if (idx < NN) sum += g_cntI[idx];
    }
    part[t] = sum;
    __syncthreads();
    for (int off = 1; off < 1024; off <<= 1) {
        int v = (t >= off) ? part[t - off] : 0;
        __syncthreads();
        part[t] += v;
        __syncthreads();
    }
    int run = part[t] - sum;   // exclusive prefix of this chunk
    for (int i = 0; i < CH; i++) {
        int idx = base + i;
        if (idx < NN) {
            g_off[idx] = run;
            g_cur[idx] = run;
            run += g_cntI[idx];
        }
    }
    if (t == 1023) g_off[NN] = NE;
}

__global__ void k_fill(const int* __restrict__ ei) {
    int e = blockIdx.x * blockDim.x + threadIdx.x;
    if (e >= NE) return;
    int src = ei[e];
    int dst = ei[NE + e];
    int pos = atomicAdd(g_cur + dst, 1);
    g_csrc[pos] = src;
}

__global__ void k_dinv() {
    int i = blockIdx.x * blockDim.x + threadIdx.x;
    if (i < NN) {
        int c = g_cntI[i];
        g_cnt[i] = (float)c;
        g_dinv[i] = rsqrtf((float)c + 1.0f);
    }
}

// ---------------- gather aggregation: agg[n] = sum_{in(n)} feat[src], 128 floats ----------------
// warp per node; lane owns one float4; unroll x2 for MLP
__global__ void k_gather_x(const float* __restrict__ x) {
    int gt = blockIdx.x * blockDim.x + threadIdx.x;
    int node = gt >> 5;
    int lane = gt & 31;
    if (node >= NN) return;
    int beg = g_off[node], end = g_off[node + 1];
    float4 acc = make_float4(0.f, 0.f, 0.f, 0.f);
    int j = beg;
    for (; j + 1 < end; j += 2) {
        int s0 = g_csrc[j];
        int s1 = g_csrc[j + 1];
        float4 a = ((const float4*)(x + (size_t)s0 * FI))[lane];
        float4 b = ((const float4*)(x + (size_t)s1 * FI))[lane];
        acc.x += a.x + b.x; acc.y += a.y + b.y;
        acc.z += a.z + b.z; acc.w += a.w + b.w;
    }
    if (j < end) {
        int s0 = g_csrc[j];
        float4 a = ((const float4*)(x + (size_t)s0 * FI))[lane];
        acc.x += a.x; acc.y += a.y; acc.z += a.z; acc.w += a.w;
    }
    ((float4*)(g_agg + (size_t)node * FI))[lane] = acc;
}

__global__ void k_gather_h1() {
    int gt = blockIdx.x * blockDim.x + threadIdx.x;
    int node = gt >> 5;
    int lane = gt & 31;
    if (node >= NN) return;
    int beg = g_off[node], end = g_off[node + 1];
    float4 acc = make_float4(0.f, 0.f, 0.f, 0.f);
    int j = beg;
    for (; j + 1 < end; j += 2) {
        int s0 = g_csrc[j];
        int s1 = g_csrc[j + 1];
        float4 a = ((const float4*)(g_h1 + (size_t)s0 * FH))[lane];
        float4 b = ((const float4*)(g_h1 + (size_t)s1 * FH))[lane];
        acc.x += a.x + b.x; acc.y += a.y + b.y;
        acc.z += a.z + b.z; acc.w += a.w + b.w;
    }
    if (j < end) {
        int s0 = g_csrc[j];
        float4 a = ((const float4*)(g_h1 + (size_t)s0 * FH))[lane];
        acc.x += a.x; acc.y += a.y; acc.z += a.z; acc.w += a.w;
    }
    ((float4*)(g_agg + (size_t)node * FI))[lane] = acc;
}

// ---------------- SAGE layer 1: h1 = relu(mean @ W1l + b1l + x @ W1r) ----------------
// static shared only; 16 nodes per block; K in 8 chunks of 16; warp owns 2 nodes, lane owns 4 cols
#define S1_NODES 16
#define S1_KC 16
__global__ void k_sage1(const float* __restrict__ x,
                        const float* __restrict__ W1l,
                        const float* __restrict__ b1l,
                        const float* __restrict__ W1r) {
    __shared__ float sWl[S1_KC * FH];      // 8KB
    __shared__ float sWr[S1_KC * FH];      // 8KB
    __shared__ float sM[S1_NODES * S1_KC]; // 1KB
    __shared__ float sX[S1_NODES * S1_KC]; // 1KB
    int t = threadIdx.x;
    int warp = t >> 5, lane = t & 31;
    int ln0 = warp * 2, ln1 = warp * 2 + 1;
    int nbase = blockIdx.x * S1_NODES;

    float4 acc0 = ((const float4*)b1l)[lane];
    float4 acc1 = acc0;

    int ld_node = t >> 4;
    int ld_kk = t & 15;
    int ld_gn = nbase + ld_node;
    float ld_scale = 1.0f / fmaxf(g_cnt[ld_gn], 1.0f);

    for (int c = 0; c < FI / S1_KC; c++) {
        int kbase = c * S1_KC;
        const float4* gWl4 = (const float4*)(W1l + kbase * FH);
        const float4* gWr4 = (const float4*)(W1r + kbase * FH);
        ((float4*)sWl)[t] = gWl4[t];
        ((float4*)sWl)[t + 256] = gWl4[t + 256];
        ((float4*)sWr)[t] = gWr4[t];
        ((float4*)sWr)[t + 256] = gWr4[t + 256];
        sM[ld_node * S1_KC + ld_kk] = g_agg[(size_t)ld_gn * FI + kbase + ld_kk] * ld_scale;
        sX[ld_node * S1_KC + ld_kk] = x[(size_t)ld_gn * FI + kbase + ld_kk];
        __syncthreads();

        const float4* wl4 = (const float4*)sWl;
        const float4* wr4 = (const float4*)sWr;
        #pragma unroll
        for (int k = 0; k < S1_KC; k++) {
            float4 wl = wl4[k * 32 + lane];
            float4 wr = wr4[k * 32 + lane];
            float m0 = sM[ln0 * S1_KC + k], x0 = sX[ln0 * S1_KC + k];
            float m1 = sM[ln1 * S1_KC + k], x1 = sX[ln1 * S1_KC + k];
            acc0.x += m0 * wl.x + x0 * wr.x;
            acc0.y += m0 * wl.y + x0 * wr.y;
            acc0.z += m0 * wl.z + x0 * wr.z;
            acc0.w += m0 * wl.w + x0 * wr.w;
            acc1.x += m1 * wl.x + x1 * wr.x;
            acc1.y += m1 * wl.y + x1 * wr.y;
            acc1.z += m1 * wl.z + x1 * wr.z;
            acc1.w += m1 * wl.w + x1 * wr.w;
        }
        __syncthreads();
    }

    int g0 = nbase + ln0, g1 = nbase + ln1;
    float4 r0 = make_float4(fmaxf(acc0.x, 0.f), fmaxf(acc0.y, 0.f), fmaxf(acc0.z, 0.f), fmaxf(acc0.w, 0.f));
    float4 r1 = make_float4(fmaxf(acc1.x, 0.f), fmaxf(acc1.y, 0.f), fmaxf(acc1.z, 0.f), fmaxf(acc1.w, 0.f));
    ((float4*)(g_h1 + (size_t)g0 * FH))[lane] = r0;
    ((float4*)(g_h1 + (size_t)g1 * FH))[lane] = r1;
}

// ---------------- SAGE layer 2: h2_pre = mean2 @ W2l + b2l + h1 @ W2r ----------------
#define S2_NODES 16
#define S2_KC 32
__global__ void k_sage2(const float* __restrict__ W2l,
                        const float* __restrict__ b2l,
                        const float* __restrict__ W2r) {
    __shared__ float sWl[S2_KC * FC];      // 8KB
    __shared__ float sWr[S2_KC * FC];      // 8KB
    __shared__ float sM[S2_NODES * S2_KC]; // 2KB
    __shared__ float sH[S2_NODES * S2_KC]; // 2KB
    int t = threadIdx.x;
    int warp = t >> 5, lane = t & 31;
    int ln0 = warp * 2, ln1 = warp * 2 + 1;
    int cA = lane, cB = lane + 32;
    int nbase = blockIdx.x * S2_NODES;

    float b0 = b2l[cA], b1 = b2l[cB];
    float a00 = b0, a01 = b1, a10 = b0, a11 = b1;

    for (int c = 0; c < FH / S2_KC; c++) {
        int kbase = c * S2_KC;
        const float4* gWl4 = (const float4*)(W2l + kbase * FC);
        const float4* gWr4 = (const float4*)(W2r + kbase * FC);
        ((float4*)sWl)[t] = gWl4[t];
        ((float4*)sWl)[t + 256] = gWl4[t + 256];
        ((float4*)sWr)[t] = gWr4[t];
        ((float4*)sWr)[t + 256] = gWr4[t + 256];
        for (int i = t; i < S2_NODES * S2_KC; i += 256) {
            int node = i >> 5;
            int kk = i & 31;
            int gn = nbase + node;
            float scale = 1.0f / fmaxf(g_cnt[gn], 1.0f);
            sM[node * S2_KC + kk] = g_agg[(size_t)gn * FH + kbase + kk] * scale;
            sH[node * S2_KC + kk] = g_h1[(size_t)gn * FH + kbase + kk];
        }
        __syncthreads();

        #pragma unroll
        for (int k = 0; k < S2_KC; k++) {
            float wlA = sWl[k * FC + cA], wlB = sWl[k * FC + cB];
            float wrA = sWr[k * FC + cA], wrB = sWr[k * FC + cB];
            float m0 = sM[ln0 * S2_KC + k], h0 = sH[ln0 * S2_KC + k];
            float m1 = sM[ln1 * S2_KC + k], h1 = sH[ln1 * S2_KC + k];
            a00 += m0 * wlA + h0 * wrA;
            a01 += m0 * wlB + h0 * wrB;
            a10 += m1 * wlA + h1 * wrA;
            a11 += m1 * wlB + h1 * wrB;
        }
        __syncthreads();
    }

    int g0 = nbase + ln0, g1 = nbase + ln1;
    g_h2[(size_t)g0 * FC + cA] = a00;
    g_h2[(size_t)g0 * FC + cB] = a01;
    g_h2[(size_t)g1 * FC + cA] = a10;
    g_h2[(size_t)g1 * FC + cB] = a11;
}

// ---------------- softmax over rows of 64 (warp per node, coalesced) ----------------
__global__ void k_softmax() {
    int gt = blockIdx.x * blockDim.x + threadIdx.x;
    int node = gt >> 5;
    int lane = gt & 31;
    if (node >= NN) return;
    float* row = g_h2 + (size_t)node * FC;
    float v0 = row[lane];
    float v1 = row[lane + 32];
    float mx = fmaxf(v0, v1);
    for (int o = 16; o > 0; o >>= 1) mx = fmaxf(mx, __shfl_xor_sync(0xFFFFFFFFu, mx, o));
    float e0 = __expf(v0 - mx), e1 = __expf(v1 - mx);
    float s = e0 + e1;
    for (int o = 16; o > 0; o >>= 1) s += __shfl_xor_sync(0xFFFFFFFFu, s, o);
    float inv = 1.0f / s;
    row[lane] = e0 * inv;
    row[lane + 32] = e1 * inv;
}

// ---------------- GCN gemm + self-loop/bias epilogue ----------------
// xw = h2 @ Wg; out = bg + dinv^2 * xw (edge term gathered after)
#define G_NODES 16
__global__ void k_gcn(const float* __restrict__ Wg,
                      const float* __restrict__ bg,
                      float* __restrict__ out) {
    __shared__ float sW[FC * FC];          // 16KB
    __shared__ float sF[G_NODES * FC];     // 4KB
    int t = threadIdx.x;
    for (int i = t; i < FC * FC; i += 256) sW[i] = Wg[i];

    int nbase = blockIdx.x * G_NODES;
    for (int i = t; i < G_NODES * FC; i += 256) {
        int node = i >> 6;
        int kk = i & 63;
        int gn = nbase + node;
        sF[node * FC + kk] = g_h2[(size_t)gn * FC + kk];
    }
    __syncthreads();

    int warp = t >> 5, lane = t & 31;
    int ln0 = warp * 2, ln1 = warp * 2 + 1;
    int cA = lane, cB = lane + 32;
    float a00 = 0.f, a01 = 0.f, a10 = 0.f, a11 = 0.f;
    #pragma unroll 8
    for (int k = 0; k < FC; k++) {
        float wA = sW[k * FC + cA], wB = sW[k * FC + cB];
        float f0 = sF[ln0 * FC + k];
        float f1 = sF[ln1 * FC + k];
        a00 += f0 * wA; a01 += f0 * wB;
        a10 += f1 * wA; a11 += f1 * wB;
    }
    int g0 = nbase + ln0, g1 = nbase + ln1;
    g_xw[(size_t)g0 * FC + cA] = a00;
    g_xw[(size_t)g0 * FC + cB] = a01;
    g_xw[(size_t)g1 * FC + cA] = a10;
    g_xw[(size_t)g1 * FC + cB] = a11;
    float bA = bg[cA], bB = bg[cB];
    float d0 = g_dinv[g0]; d0 *= d0;
    float d1 = g_dinv[g1]; d1 *= d1;
    out[(size_t)g0 * FC + cA] = bA + d0 * a00;
    out[(size_t)g0 * FC + cB] = bB + d0 * a01;
    out[(size_t)g1 * FC + cA] = bA + d1 * a10;
    out[(size_t)g1 * FC + cB] = bB + d1 * a11;
}

// ---------------- GCN edge gather: out[n] += dinv[n] * sum dinv[src]*xw[src] ----------------
__global__ void k_ggather(float* __restrict__ out) {
    int gt = blockIdx.x * blockDim.x + threadIdx.x;
    int node = gt >> 5;
    int lane = gt & 31;
    if (node >= NN) return;
    int beg = g_off[node], end = g_off[node + 1];
    float accA = 0.f, accB = 0.f;
    for (int j = beg; j < end; j++) {
        int s = g_csrc[j];
        float ds = g_dinv[s];
        const float* r = g_xw + (size_t)s * FC;
        accA += ds * r[lane];
        accB += ds * r[lane + 32];
    }
    float dn = g_dinv[node];
    float* row = out + (size_t)node * FC;
    row[lane] += dn * accA;
    row[lane + 32] += dn * accB;
}

// ---------------- launch ----------------
static void hx_check(const char* name, bool docheck, bool* bad) {
    if (!docheck || *bad) return;
    cudaError_t e = cudaStreamSynchronize(0);
    if (e != cudaSuccess) {
        fprintf(stderr, "HXDBG fault after %s: %s\n", name, cudaGetErrorString(e));
        fflush(stderr);
        *bad = true;
    }
}

extern "C" void kernel_launch(void* const* d_in, const int* in_sizes, int n_in,
                              void* d_out, int out_size) {
    const float* x   = (const float*)d_in[0];
    const int* ei    = (const int*)d_in[1];   // INT32 [2, E] — the fix
    const float* W1l = (const float*)d_in[2];
    const float* b1l = (const float*)d_in[3];
    const float* W1r = (const float*)d_in[4];
    const float* W2l = (const float*)d_in[5];
    const float* b2l = (const float*)d_in[6];
    const float* W2r = (const float*)d_in[7];
    const float* Wg  = (const float*)d_in[8];
    const float* bg  = (const float*)d_in[9];
    float* out = (float*)d_out;

    // Fault attribution (correctness run only; no-ops during graph capture).
    cudaStreamCaptureStatus st = cudaStreamCaptureStatusNone;
    cudaStreamIsCapturing(0, &st);
    bool docheck = (st == cudaStreamCaptureStatusNone);
    bool bad = false;

    // CSR build (by dst)
    k_zero_cnt<<<(NN + 255) / 256, 256>>>();
    hx_check("k_zero_cnt", docheck, &bad);
    k_count<<<(NE + 255) / 256, 256>>>(ei);
    hx_check("k_count", docheck, &bad);
    k_scan<<<1, 1024>>>();
    hx_check("k_scan", docheck, &bad);
    k_fill<<<(NE + 255) / 256, 256>>>(ei);
    hx_check("k_fill", docheck, &bad);
    k_dinv<<<(NN + 255) / 256, 256>>>();
    hx_check("k_dinv", docheck, &bad);

    // SAGE layer 1
    k_gather_x<<<(NN * 32 + 255) / 256, 256>>>(x);
    hx_check("k_gather_x", docheck, &bad);
    k_sage1<<<NN / S1_NODES, 256>>>(x, W1l, b1l, W1r);
    hx_check("k_sage1", docheck, &bad);

    // SAGE layer 2
    k_gather_h1<<<(NN * 32 + 255) / 256, 256>>>();
    hx_check("k_gather_h1", docheck, &bad);
    k_sage2<<<NN / S2_NODES, 256>>>(W2l, b2l, W2r);
    hx_check("k_sage2", docheck, &bad);
    k_softmax<<<(NN * 32 + 255) / 256, 256>>>();
    hx_check("k_softmax", docheck, &bad);

    // GCN
    k_gcn<<<NN / G_NODES, 256>>>(Wg, bg, out);
    hx_check("k_gcn", docheck, &bad);
    k_ggather<<<(NN * 32 + 255) / 256, 256>>>(out);
    hx_check("k_ggather", docheck, &bad);
}